// round 5
// baseline (speedup 1.0000x reference)
#include <cuda_runtime.h>
#include <cuda_bf16.h>

// SimSiam loss, algebraically reduced:
//   loss = -0.5 * sum_c( P_c . Z_c  -  sum_{i in c} pn_i.zn_i ) / npairs
// where P_c/Z_c are per-class sums of L2-normalized rows and
// npairs = sum_c m_c*(m_c-1)/2.   O(n*d) work, no 8192x8192 GEMM.
//
// Scratch invariant: all accumulated __device__ scratch is ZERO at
// kernel_launch entry (zero at module load; final_kernel re-zeros before
// finishing). g_Spart/g_Ppart are plain-stored (not accumulated) each call.
//
// No single-address atomic funnels: per-class vector REDs spread over 128K
// addresses; diag partials spread over 64 slots; final reduction uses plain
// per-block stores + a last-block-done parallel sum.

#define NCLASS 512
#define D      128
#define EPS    1e-8f
#define FBLK   64          // final_kernel grid size

__device__ float              g_P[NCLASS * D];
__device__ float              g_Z[NCLASS * D];
__device__ int                g_cnt[NCLASS];
__device__ double             g_Dpart[FBLK];   // diag partials (accumulated)
__device__ double             g_Spart[FBLK];   // per-final-block dot sums
__device__ unsigned long long g_Ppart[FBLK];   // per-final-block pair counts
__device__ unsigned int       g_done;

// 128-bit reduction into global memory (sm_90+), no return value.
__device__ __forceinline__ void red_add_v4(float* p, float x, float y, float z, float w) {
    asm volatile("red.global.add.v4.f32 [%0], {%1, %2, %3, %4};"
                 :: "l"(p), "f"(x), "f"(y), "f"(z), "f"(w) : "memory");
}

// ---------------------------------------------------------------------------
// One warp per row: float4 loads, warp-reduce norms + dot, scatter normalized
// rows into per-class sums with 128-bit vector atomics. In-block dtype sniff:
// warp 0 reads the first 64 int64-view slots (512 B, in-bounds either way);
// an int32 buffer misdetects only if 64 consecutive odd labels are 0.
__global__ void accum_kernel(const float* __restrict__ ps,
                             const float* __restrict__ zs,
                             const void*  __restrict__ tgv,
                             int n_rows) {
    __shared__ double sdp[8];
    __shared__ int    s_is64;

    int warp_in_blk = threadIdx.x >> 5;
    int lane        = threadIdx.x & 31;
    int warp        = (blockIdx.x * blockDim.x + threadIdx.x) >> 5;

    if (warp_in_blk == 0) {
        const long long* t64 = (const long long*)tgv;
        int nslots = n_rows / 2;
        int k = (nslots < 64) ? nslots : 64;
        int bad = 0;
        for (int i = lane; i < k; i += 32) {
            long long v = __ldg(&t64[i]);
            if (v < 0 || v >= NCLASS) bad = 1;
        }
        bad = __any_sync(0xFFFFFFFFu, bad);
        if (lane == 0) s_is64 = !bad;
    }
    __syncthreads();
    int is64 = s_is64;

    double diag = 0.0;
    if (warp < n_rows) {
        float4 a = reinterpret_cast<const float4*>(ps)[warp * (D / 4) + lane];
        float4 b = reinterpret_cast<const float4*>(zs)[warp * (D / 4) + lane];

        float sa = a.x * a.x + a.y * a.y + a.z * a.z + a.w * a.w;
        float sb = b.x * b.x + b.y * b.y + b.z * b.z + b.w * b.w;
        float dp = a.x * b.x + a.y * b.y + a.z * b.z + a.w * b.w;

        #pragma unroll
        for (int o = 16; o > 0; o >>= 1) {
            sa += __shfl_xor_sync(0xFFFFFFFFu, sa, o);
            sb += __shfl_xor_sync(0xFFFFFFFFu, sb, o);
            dp += __shfl_xor_sync(0xFFFFFFFFu, dp, o);
        }

        float invp = 1.0f / fmaxf(sqrtf(sa), EPS);
        float invz = 1.0f / fmaxf(sqrtf(sb), EPS);

        int t;
        if (is64) t = (int)reinterpret_cast<const long long*>(tgv)[warp];
        else      t = reinterpret_cast<const int*>(tgv)[warp];

        red_add_v4(&g_P[t * D + lane * 4], a.x * invp, a.y * invp, a.z * invp, a.w * invp);
        red_add_v4(&g_Z[t * D + lane * 4], b.x * invz, b.y * invz, b.z * invz, b.w * invz);

        if (lane == 0) {
            atomicAdd(&g_cnt[t], 1);
            diag = (double)(dp * invp * invz);
        }
    }
    if (lane == 0) sdp[warp_in_blk] = diag;
    __syncthreads();
    if (threadIdx.x == 0) {
        double s = sdp[0] + sdp[1] + sdp[2] + sdp[3]
                 + sdp[4] + sdp[5] + sdp[6] + sdp[7];
        // spread over 64 slots -> no single-address funnel
        atomicAdd(&g_Dpart[blockIdx.x & (FBLK - 1)], s);
    }
}

// ---------------------------------------------------------------------------
// Per-class dot (warp per class, 8 classes/block), pair count, scratch
// re-zero, per-block PLAIN stores of partials, last-block parallel epilogue.
__global__ void final_kernel(float* __restrict__ out) {
    __shared__ float              sdot[8];
    __shared__ unsigned long long spair[8];
    __shared__ int                s_last;

    int lane = threadIdx.x & 31;
    int wid  = threadIdx.x >> 5;                 // 0..7
    int c    = blockIdx.x * 8 + wid;
    int idx  = c * (D / 4) + lane;

    float4 p = reinterpret_cast<const float4*>(g_P)[idx];
    float4 z = reinterpret_cast<const float4*>(g_Z)[idx];
    float dot = p.x * z.x + p.y * z.y + p.z * z.z + p.w * z.w;
    #pragma unroll
    for (int o = 16; o > 0; o >>= 1)
        dot += __shfl_xor_sync(0xFFFFFFFFu, dot, o);

    unsigned long long m = (unsigned long long)g_cnt[c];
    if (lane == 0) {
        sdot[wid]  = dot;
        spair[wid] = m * (m - 1ull) / 2ull;
    }

    // Re-zero the slices this block owns (restores launch-entry invariant).
    float4 zero4 = make_float4(0.f, 0.f, 0.f, 0.f);
    reinterpret_cast<float4*>(g_P)[idx] = zero4;
    reinterpret_cast<float4*>(g_Z)[idx] = zero4;
    if (lane == 0) g_cnt[c] = 0;

    __syncthreads();
    if (threadIdx.x == 0) {
        double s = (double)sdot[0] + (double)sdot[1] + (double)sdot[2] + (double)sdot[3]
                 + (double)sdot[4] + (double)sdot[5] + (double)sdot[6] + (double)sdot[7];
        unsigned long long pr = spair[0] + spair[1] + spair[2] + spair[3]
                              + spair[4] + spair[5] + spair[6] + spair[7];
        g_Spart[blockIdx.x] = s;       // plain store, no atomic
        g_Ppart[blockIdx.x] = pr;
        __threadfence();
        unsigned int done = atomicAdd(&g_done, 1u);
        s_last = (done == (unsigned int)(FBLK - 1));
    }
    __syncthreads();

    if (s_last) {
        __threadfence();  // acquire side: observe all blocks' partial stores
        // threads 0..63 load one slot each of the three partial arrays
        double    sv = 0.0, dv = 0.0;
        unsigned long long pv = 0ull;
        if (threadIdx.x < FBLK) {
            sv = g_Spart[threadIdx.x];
            dv = g_Dpart[threadIdx.x];
            pv = g_Ppart[threadIdx.x];
            g_Dpart[threadIdx.x] = 0.0;   // re-zero accumulated scratch
        }
        // reduce 64 lanes -> warp 0 lane 0 (two warps participate)
        __shared__ double sv1, dv1; __shared__ unsigned long long pv1;
        #pragma unroll
        for (int o = 16; o > 0; o >>= 1) {
            sv += __shfl_xor_sync(0xFFFFFFFFu, sv, o);
            dv += __shfl_xor_sync(0xFFFFFFFFu, dv, o);
            pv += __shfl_xor_sync(0xFFFFFFFFu, pv, o);
        }
        if (threadIdx.x == 32) { sv1 = sv; dv1 = dv; pv1 = pv; }
        __syncthreads();
        if (threadIdx.x == 0) {
            double S  = sv + sv1 - (dv + dv1);
            unsigned long long pr = pv + pv1;
            double np = (pr > 0ull) ? (double)pr : 1.0;
            out[0] = (float)(-0.5 * S / np);
            g_done = 0u;
        }
    }
}

// ---------------------------------------------------------------------------
extern "C" void kernel_launch(void* const* d_in, const int* in_sizes, int n_in,
                              void* d_out, int out_size) {
    const float* ps  = (const float*)d_in[0];
    const float* zs  = (const float*)d_in[1];
    const void*  tgt = d_in[2];
    float*       out = (float*)d_out;

    int n_rows = in_sizes[0] / D;   // 8192

    accum_kernel<<<(n_rows + 7) / 8, 256>>>(ps, zs, tgt, n_rows);
    final_kernel<<<FBLK, 256>>>(out);
}